// round 11
// baseline (speedup 1.0000x reference)
#include <cuda_runtime.h>
#include <cuda_fp16.h>
#include <math.h>
#include <cstdint>

#define IMW 512
#define IMH 512
#define NCH 12
#define NBINS 256
#define NT 256          // 8 warps; warp w handles row gy0+w, 64 px wide
#define TILE_W 64

struct Params { const float* p[27]; };

__device__ double g_sumsq[2];                    // [0]=x, [1]=delta
__device__ unsigned int g_hist[2][NCH][NBINS];   // [0]=x, [1]=delta

// precomputed MMA B-fragments + biases
#define TILES_PER_PRED 26
#define NFRAG (3 * TILES_PER_PRED * 32)
__device__ uint2 g_bf[NFRAG];
__device__ uint32_t g_bias2[3][3][4][4];         // half2 (b[n0], b[n0+1])
__device__ float g_b3[3];

#define ZTOTAL (2 * NCH * NBINS)
__global__ void zero_slice_kernel(int slice) {   // 4 slices
    const int per = (ZTOTAL + 3) / 4;
    int i = slice * per + blockIdx.x * blockDim.x + threadIdx.x;
    if (i < (slice + 1) * per && i < ZTOTAL) ((unsigned int*)g_hist)[i] = 0u;
    if (slice == 0 && blockIdx.x == 0 && threadIdx.x < 2) g_sumsq[threadIdx.x] = 0.0;
}

__device__ __forceinline__ uint32_t packh2(float lo, float hi) {
    __half2 h = __floats2half2_rn(lo, hi);
    return *reinterpret_cast<uint32_t*>(&h);
}
__device__ __forceinline__ __half2 u2h(uint32_t u) { return *reinterpret_cast<__half2*>(&u); }

// m16n8k16 fp16 MMA, fp32 accumulate (in-place D += A*B)
__device__ __forceinline__ void mma16816(float* d, const uint32_t* a, const uint32_t* b) {
    asm volatile(
        "mma.sync.aligned.m16n8k16.row.col.f32.f16.f16.f32 "
        "{%0,%1,%2,%3}, {%4,%5,%6,%7}, {%8,%9}, {%0,%1,%2,%3};"
        : "+f"(d[0]), "+f"(d[1]), "+f"(d[2]), "+f"(d[3])
        : "r"(a[0]), "r"(a[1]), "r"(a[2]), "r"(a[3]), "r"(b[0]), "r"(b[1]));
}

// one-time fragment pack (weights -> fp16 mma B-fragment layout)
__global__ void pack_weights_kernel(Params prm) {
    const int tid = blockIdx.x * blockDim.x + threadIdx.x;
    for (int i = tid; i < NFRAG; i += gridDim.x * blockDim.x) {
        int p = i / (TILES_PER_PRED * 32);
        int rem = i % (TILES_PER_PRED * 32);
        int tile = rem / 32, ln = rem % 32;
        int ltig = ln & 3, lg = ln >> 2;
        float w[4];
        if (tile < 24) {
            int l = tile / 8, r8 = tile % 8, kt = r8 / 4, nt = r8 % 4;
            int n = nt * 8 + lg;
            int kb = kt * 16 + 2 * ltig;
            int ks[4] = {kb, kb + 1, kb + 8, kb + 9};
            if (l == 0) {
                const float* wT = prm.p[p * 9 + 0];
                const float* wL = prm.p[p * 9 + 2];
#pragma unroll
                for (int j = 0; j < 4; ++j) {
                    int k = ks[j];
                    w[j] = (k < 21) ? wT[n * 21 + k] : (k < 24 ? wL[n * 3 + (k - 21)] : 0.f);
                }
            } else {
                const float* wm = prm.p[p * 9 + (l == 1 ? 3 : 5)];
#pragma unroll
                for (int j = 0; j < 4; ++j) w[j] = wm[n * 32 + ks[j]];
            }
        } else {
            int kt = tile - 24;
            const float* w3 = prm.p[p * 9 + 7];
            int kb = kt * 16 + 2 * ltig;
#pragma unroll
            for (int j = 0; j < 4; ++j) {
                int k = kb + (j & 1) + (j >> 1) * 8;
                w[j] = (lg == 0) ? w3[k] : 0.f;
            }
        }
        uint2 v;
        v.x = packh2(w[0], w[1]);
        v.y = packh2(w[2], w[3]);
        g_bf[i] = v;
    }
    // biases
    for (int i = tid; i < 3 * 3 * 16; i += gridDim.x * blockDim.x) {
        int p = i / 48, r = i % 48, l = r / 16, q = r % 16;
        int nt = q / 4, tg = q % 4;
        const float* b = prm.p[p * 9 + (l == 0 ? 1 : (l == 1 ? 4 : 6))];
        int n0 = nt * 8 + 2 * tg;
        g_bias2[p][l][nt][tg] = packh2(b[n0], b[n0 + 1]);
    }
    if (tid < 3) g_b3[tid] = prm.p[tid * 9 + 8][0];
}

__global__ __launch_bounds__(NT) void predict_kernel(const float* __restrict__ x) {
    __shared__ __align__(16) uint2 s_bf[NFRAG];     // 19.5 KB
    __shared__ float s_tile[11][72];                // 8+3 rows, 64+6 cols used
    __shared__ uint32_t s_bias2[3][3][4][4];        // half2 pairs
    __shared__ float s_b3[3];
    __shared__ unsigned int s_hist[2][NBINS];
    __shared__ double s_red[2][NT / 32];

    const int lane = threadIdx.x;
    const int wr   = threadIdx.y;       // warp row (0..7)
    const int tid  = wr * 32 + lane;
    const int tig  = lane & 3;
    const int g    = lane >> 2;
    const int ch   = blockIdx.z;
    const int gx0  = blockIdx.x * TILE_W;
    const int gy0  = blockIdx.y * 8;

    for (int i = tid; i < 2 * NBINS; i += NT) ((unsigned int*)s_hist)[i] = 0u;

    // coalesced fragment copy (uint4: 2 fragments per load)
    {
        const uint4* src = (const uint4*)g_bf;
        uint4* dst = (uint4*)s_bf;
        for (int i = tid; i < NFRAG / 2; i += NT) dst[i] = src[i];
    }
    for (int i = tid; i < 3 * 3 * 16; i += NT) ((uint32_t*)s_bias2)[i] = ((const uint32_t*)g_bias2)[i];
    if (tid < 3) s_b3[tid] = g_b3[tid];

    // ---- stage input tile with halo (top 3 rows, left/right 3 cols) ----
    const float* xch = x + (size_t)ch * IMH * IMW;
    for (int i = tid; i < 11 * 70; i += NT) {
        int r = i / 70, c = i % 70;
        int gr = gy0 - 3 + r, gc = gx0 - 3 + c;
        float v = 0.f;
        if (gr >= 0 && gc >= 0 && gc < IMW) v = xch[gr * IMW + gc];
        s_tile[r][c] = v;
    }
    __syncthreads();

    const __half2 C001 = __float2half2_rn(0.01f);
    double acc_x = 0.0, acc_d = 0.0;

#pragma unroll 1
    for (int m = 0; m < 4; ++m) {
        const int px0 = m * 16 + g;        // row g of m-tile
        const int px1 = px0 + 8;           // row g+8

        // ---- build layer-0 A fragments from taps ----
        uint32_t A0[2][4];
#pragma unroll
        for (int kt = 0; kt < 2; ++kt) {
            const int kb = kt * 16 + 2 * tig;
#define TAP(px, k) ((k) < 21 ? s_tile[wr + (k) / 7][(px) + (k) % 7] : s_tile[wr + 3][(px) + (k) - 21])
            A0[kt][0] = packh2(TAP(px0, kb), TAP(px0, kb + 1));
            A0[kt][1] = packh2(TAP(px1, kb), TAP(px1, kb + 1));
            if (kt == 0) {
                A0[kt][2] = packh2(TAP(px0, kb + 8), TAP(px0, kb + 9));
                A0[kt][3] = packh2(TAP(px1, kb + 8), TAP(px1, kb + 9));
            } else {
                A0[kt][2] = 0u;
                A0[kt][3] = 0u;
            }
#undef TAP
        }

        float ph[3][2];
#pragma unroll 1
        for (int p = 0; p < 3; ++p) {
            uint32_t A[2][4];
#pragma unroll
            for (int kt = 0; kt < 2; ++kt)
#pragma unroll
                for (int j = 0; j < 4; ++j) A[kt][j] = A0[kt][j];

#pragma unroll
            for (int l = 0; l < 3; ++l) {
                float D[4][4];
#pragma unroll
                for (int nt = 0; nt < 4; ++nt)
#pragma unroll
                    for (int j = 0; j < 4; ++j) D[nt][j] = 0.f;

#pragma unroll
                for (int kt = 0; kt < 2; ++kt) {
#pragma unroll
                    for (int nt = 0; nt < 4; ++nt) {
                        uint2 bv = s_bf[(p * TILES_PER_PRED + l * 8 + kt * 4 + nt) * 32 + lane];
                        uint32_t br[2] = {bv.x, bv.y};
                        mma16816(D[nt], A[kt], br);
                    }
                }
                // fp16x2 epilogue: pack D pairs, bias hadd2, leaky hmax2
#pragma unroll
                for (int nt = 0; nt < 4; ++nt) {
                    __half2 b2 = u2h(s_bias2[p][l][nt][tig]);
                    __half2 h01 = __hadd2(u2h(packh2(D[nt][0], D[nt][1])), b2);
                    __half2 h23 = __hadd2(u2h(packh2(D[nt][2], D[nt][3])), b2);
                    h01 = __hmax2(h01, __hmul2(h01, C001));
                    h23 = __hmax2(h23, __hmul2(h23, C001));
                    A[nt / 2][(nt % 2) * 2 + 0] = *reinterpret_cast<uint32_t*>(&h01);
                    A[nt / 2][(nt % 2) * 2 + 1] = *reinterpret_cast<uint32_t*>(&h23);
                }
            }

            // ---- head: 32 -> 1 via mma ----
            float Dh[4] = {0.f, 0.f, 0.f, 0.f};
            {
                uint2 b0 = s_bf[(p * TILES_PER_PRED + 24) * 32 + lane];
                uint2 b1 = s_bf[(p * TILES_PER_PRED + 25) * 32 + lane];
                uint32_t br0[2] = {b0.x, b0.y};
                uint32_t br1[2] = {b1.x, b1.y};
                mma16816(Dh, A[0], br0);
                mma16816(Dh, A[1], br1);
            }
            float b3 = s_b3[p];
            ph[p][0] = fminf(fmaxf(Dh[0] + b3, -1.f), 1.f);   // row g
            ph[p][1] = fminf(fmaxf(Dh[2] + b3, -1.f), 1.f);   // row g+8
        }

        // ---- stats for this m-tile (tig==0 lanes own 2 pixels) ----
        if (tig == 0) {
#pragma unroll
            for (int hh = 0; hh < 2; ++hh) {
                int px = px0 + hh * 8;
                float x0 = s_tile[wr + 3][px + 3];
                float pa = ph[0][hh], pb = ph[1][hh], pc = ph[2][hh];
                float med = fmaxf(fminf(pa, fmaxf(pb, pc)), fminf(pb, pc));
                float delta = fmodf(x0 - med + 1.0f, 2.0f) - 1.0f;

                if (x0 >= -1.f && x0 <= 1.f) {
                    int idx = (int)floorf((x0 + 1.f) * 128.f);
                    idx = min(max(idx, 0), NBINS - 1);
                    atomicAdd(&s_hist[0][idx], 1u);
                }
                if (delta >= -1.f && delta <= 1.f) {
                    int idx = (int)floorf((delta + 1.f) * 128.f);
                    idx = min(max(idx, 0), NBINS - 1);
                    atomicAdd(&s_hist[1][idx], 1u);
                }
                acc_x += (double)x0 * (double)x0;
                acc_d += (double)delta * (double)delta;
            }
        }
    }

    // ---- reductions ----
#pragma unroll
    for (int o = 16; o > 0; o >>= 1) {
        acc_x += __shfl_down_sync(0xffffffffu, acc_x, o);
        acc_d += __shfl_down_sync(0xffffffffu, acc_d, o);
    }
    if (lane == 0) { s_red[0][wr] = acc_x; s_red[1][wr] = acc_d; }
    __syncthreads();
    if (tid == 0) {
        double sx = 0.0, sd = 0.0;
#pragma unroll
        for (int i = 0; i < NT / 32; ++i) { sx += s_red[0][i]; sd += s_red[1][i]; }
        atomicAdd(&g_sumsq[0], sx);
        atomicAdd(&g_sumsq[1], sd);
    }
    if (tid < NBINS) {
        unsigned c0 = s_hist[0][tid], c1 = s_hist[1][tid];
        if (c0) atomicAdd(&g_hist[0][ch][tid], c0);
        if (c1) atomicAdd(&g_hist[1][ch][tid], c1);
    }
}

__global__ void finalize_kernel(float* out) {
    __shared__ double s_ent[2][8];
    const int tid = threadIdx.x;
    double e0 = 0.0, e1 = 0.0;
    const double res = (double)(IMH * IMW);
    for (int i = tid; i < NCH * NBINS; i += 256) {
        unsigned c0 = ((const unsigned*)g_hist[0])[i];
        unsigned c1 = ((const unsigned*)g_hist[1])[i];
        if (c0) { double pp = (double)c0 / res; e0 -= pp * log2(pp); }
        if (c1) { double pp = (double)c1 / res; e1 -= pp * log2(pp); }
    }
#pragma unroll
    for (int o = 16; o > 0; o >>= 1) {
        e0 += __shfl_down_sync(0xffffffffu, e0, o);
        e1 += __shfl_down_sync(0xffffffffu, e1, o);
    }
    if ((tid & 31) == 0) { s_ent[0][tid >> 5] = e0; s_ent[1][tid >> 5] = e1; }
    __syncthreads();
    if (tid == 0) {
        double E0 = 0.0, E1 = 0.0;
#pragma unroll
        for (int i = 0; i < 8; ++i) { E0 += s_ent[0][i]; E1 += s_ent[1][i]; }
        const double N = (double)NCH * IMH * IMW;
        out[0] = (float)(255.0 * sqrt(g_sumsq[1] / N));   // loss1
        out[1] = (float)(255.0 * sqrt(g_sumsq[0] / N));   // loss0
        out[2] = (float)(E0 / (8.0 * NCH));               // invCR0
        out[3] = (float)(E1 / (8.0 * NCH));               // invCR1
    }
}

extern "C" void kernel_launch(void* const* d_in, const int* in_sizes, int n_in,
                              void* d_out, int out_size) {
    const float* x = (const float*)d_in[0];
    Params prm;
    for (int i = 0; i < 27; ++i) prm.p[i] = (const float*)d_in[1 + i];

    // launch order keeps predict_kernel at index 5 for ncu -s 5 -c 1
    pack_weights_kernel<<<4, 256>>>(prm);                 // 0
    const int per = (ZTOTAL + 3) / 4;
    for (int s = 0; s < 4; ++s)
        zero_slice_kernel<<<(per + 255) / 256, 256>>>(s); // 1-4

    dim3 grid(IMW / TILE_W, IMH / 8, NCH);
    dim3 block(32, 8);
    predict_kernel<<<grid, block>>>(x);                   // 5
    finalize_kernel<<<1, 256>>>((float*)d_out);
}

// round 12
// speedup vs baseline: 1.3898x; 1.3898x over previous
#include <cuda_runtime.h>
#include <cuda_fp16.h>
#include <math.h>
#include <cstdint>

#define IMW 512
#define IMH 512
#define NCH 12
#define NBINS 256
#define NT 256          // 8 warps; warp w handles row gy0+w, 32 px wide

struct Params { const float* p[27]; };

__device__ double g_sumsq[2];                    // [0]=x, [1]=delta
__device__ unsigned int g_hist[2][NCH][NBINS];   // [0]=x, [1]=delta

// precomputed MMA B-fragments + biases
#define TILES_PER_PRED 26
#define NFRAG (3 * TILES_PER_PRED * 32)
__device__ uint2 g_bf[NFRAG];
__device__ float2 g_bias2[3][3][4][4];           // (b[n0], b[n0+1])
__device__ float g_b3[3];

#define ZTOTAL (2 * NCH * NBINS)
__global__ void zero_slice_kernel(int slice) {   // 4 slices
    const int per = (ZTOTAL + 3) / 4;
    int i = slice * per + blockIdx.x * blockDim.x + threadIdx.x;
    if (i < (slice + 1) * per && i < ZTOTAL) ((unsigned int*)g_hist)[i] = 0u;
    if (slice == 0 && blockIdx.x == 0 && threadIdx.x < 2) g_sumsq[threadIdx.x] = 0.0;
}

__device__ __forceinline__ float leaky(float v) { return fmaxf(v, 0.01f * v); }

__device__ __forceinline__ uint32_t packh2(float lo, float hi) {
    __half2 h = __floats2half2_rn(lo, hi);
    return *reinterpret_cast<uint32_t*>(&h);
}

// m16n8k16 fp16 MMA, fp32 accumulate (in-place D += A*B)
__device__ __forceinline__ void mma16816(float* d, const uint32_t* a, const uint32_t* b) {
    asm volatile(
        "mma.sync.aligned.m16n8k16.row.col.f32.f16.f16.f32 "
        "{%0,%1,%2,%3}, {%4,%5,%6,%7}, {%8,%9}, {%0,%1,%2,%3};"
        : "+f"(d[0]), "+f"(d[1]), "+f"(d[2]), "+f"(d[3])
        : "r"(a[0]), "r"(a[1]), "r"(a[2]), "r"(a[3]), "r"(b[0]), "r"(b[1]));
}

// one-time fragment pack (weights -> fp16 mma B-fragment layout)
__global__ void pack_weights_kernel(Params prm) {
    const int tid = blockIdx.x * blockDim.x + threadIdx.x;
    for (int i = tid; i < NFRAG; i += gridDim.x * blockDim.x) {
        int p = i / (TILES_PER_PRED * 32);
        int rem = i % (TILES_PER_PRED * 32);
        int tile = rem / 32, ln = rem % 32;
        int ltig = ln & 3, lg = ln >> 2;
        float w[4];
        if (tile < 24) {
            int l = tile / 8, r8 = tile % 8, kt = r8 / 4, nt = r8 % 4;
            int n = nt * 8 + lg;
            int kb = kt * 16 + 2 * ltig;
            int ks[4] = {kb, kb + 1, kb + 8, kb + 9};
            if (l == 0) {
                const float* wT = prm.p[p * 9 + 0];
                const float* wL = prm.p[p * 9 + 2];
#pragma unroll
                for (int j = 0; j < 4; ++j) {
                    int k = ks[j];
                    w[j] = (k < 21) ? wT[n * 21 + k] : (k < 24 ? wL[n * 3 + (k - 21)] : 0.f);
                }
            } else {
                const float* wm = prm.p[p * 9 + (l == 1 ? 3 : 5)];
#pragma unroll
                for (int j = 0; j < 4; ++j) w[j] = wm[n * 32 + ks[j]];
            }
        } else {
            int kt = tile - 24;
            const float* w3 = prm.p[p * 9 + 7];
            int kb = kt * 16 + 2 * ltig;
#pragma unroll
            for (int j = 0; j < 4; ++j) {
                int k = kb + (j & 1) + (j >> 1) * 8;
                w[j] = (lg == 0) ? w3[k] : 0.f;
            }
        }
        uint2 v;
        v.x = packh2(w[0], w[1]);
        v.y = packh2(w[2], w[3]);
        g_bf[i] = v;
    }
    // biases
    for (int i = tid; i < 3 * 3 * 16; i += gridDim.x * blockDim.x) {
        int p = i / 48, r = i % 48, l = r / 16, q = r % 16;
        int nt = q / 4, tg = q % 4;
        const float* b = prm.p[p * 9 + (l == 0 ? 1 : (l == 1 ? 4 : 6))];
        int n0 = nt * 8 + 2 * tg;
        g_bias2[p][l][nt][tg] = make_float2(b[n0], b[n0 + 1]);
    }
    if (tid < 3) g_b3[tid] = prm.p[tid * 9 + 8][0];
}

__global__ __launch_bounds__(NT) void predict_kernel(const float* __restrict__ x) {
    __shared__ __align__(16) uint2 s_bf[NFRAG];     // 19.5 KB
    __shared__ float s_tile[11][40];                // 8 rows + 3 halo, 32 cols + 6 halo (38 used)
    __shared__ float2 s_bias2[3][3][4][4];
    __shared__ float s_b3[3];
    __shared__ unsigned int s_hist[2][NBINS];
    __shared__ double s_red[2][NT / 32];

    const int lane = threadIdx.x;
    const int wr   = threadIdx.y;       // warp row (0..7)
    const int tid  = wr * 32 + lane;
    const int tig  = lane & 3;          // thread-in-group
    const int g    = lane >> 2;         // group id (row base)
    const int ch   = blockIdx.z;
    const int gx0  = blockIdx.x * 32;
    const int gy0  = blockIdx.y * 8;

    for (int i = tid; i < 2 * NBINS; i += NT) ((unsigned int*)s_hist)[i] = 0u;

    // coalesced fragment copy (uint4: 2 fragments per load)
    {
        const uint4* src = (const uint4*)g_bf;
        uint4* dst = (uint4*)s_bf;
#pragma unroll
        for (int j = 0; j < NFRAG / 2 / NT + 1; ++j) {
            int i = j * NT + tid;
            if (i < NFRAG / 2) dst[i] = src[i];
        }
    }
    for (int i = tid; i < 3 * 3 * 16; i += NT) ((float2*)s_bias2)[i] = ((const float2*)g_bias2)[i];
    if (tid < 3) s_b3[tid] = g_b3[tid];

    // ---- stage input tile with halo (top 3 rows, left/right 3 cols) ----
    const float* xch = x + (size_t)ch * IMH * IMW;
    for (int i = tid; i < 11 * 38; i += NT) {
        int r = i / 38, c = i % 38;
        int gr = gy0 - 3 + r, gc = gx0 - 3 + c;
        float v = 0.f;
        if (gr >= 0 && gc >= 0 && gc < IMW) v = xch[gr * IMW + gc];
        s_tile[r][c] = v;
    }
    __syncthreads();

    float ph[3][2][2];   // [pred][mtile][rowhalf], valid at tig==0
    double acc_x = 0.0, acc_d = 0.0;

#pragma unroll 1
    for (int m = 0; m < 2; ++m) {
        const int px0 = m * 16 + g;        // row g
        const int px1 = px0 + 8;           // row g+8

        // ---- build layer-0 A fragments from taps ----
        uint32_t A0[2][4];
#pragma unroll
        for (int kt = 0; kt < 2; ++kt) {
            const int kb = kt * 16 + 2 * tig;
#define TAP(px, k) ((k) < 21 ? s_tile[wr + (k) / 7][(px) + (k) % 7] : s_tile[wr + 3][(px) + (k) - 21])
            A0[kt][0] = packh2(TAP(px0, kb), TAP(px0, kb + 1));
            A0[kt][1] = packh2(TAP(px1, kb), TAP(px1, kb + 1));
            if (kt == 0) {
                A0[kt][2] = packh2(TAP(px0, kb + 8), TAP(px0, kb + 9));
                A0[kt][3] = packh2(TAP(px1, kb + 8), TAP(px1, kb + 9));
            } else {
                A0[kt][2] = 0u;   // k >= 24 taps are zero
                A0[kt][3] = 0u;
            }
#undef TAP
        }

#pragma unroll 1
        for (int p = 0; p < 3; ++p) {
            uint32_t A[2][4];
#pragma unroll
            for (int kt = 0; kt < 2; ++kt)
#pragma unroll
                for (int j = 0; j < 4; ++j) A[kt][j] = A0[kt][j];

            // ---- layers 0,1,2 ----
#pragma unroll
            for (int l = 0; l < 3; ++l) {
                float D[4][4];
#pragma unroll
                for (int nt = 0; nt < 4; ++nt)
#pragma unroll
                    for (int j = 0; j < 4; ++j) D[nt][j] = 0.f;

#pragma unroll
                for (int kt = 0; kt < 2; ++kt) {
#pragma unroll
                    for (int nt = 0; nt < 4; ++nt) {
                        uint2 bv = s_bf[(p * TILES_PER_PRED + l * 8 + kt * 4 + nt) * 32 + lane];
                        uint32_t br[2] = {bv.x, bv.y};
                        mma16816(D[nt], A[kt], br);
                    }
                }
                // epilogue: bias + leaky + repack into next A (lane-local!)
#pragma unroll
                for (int nt = 0; nt < 4; ++nt) {
                    float2 b2 = s_bias2[p][l][nt][tig];
                    float v0 = leaky(D[nt][0] + b2.x);
                    float v1 = leaky(D[nt][1] + b2.y);
                    float v2 = leaky(D[nt][2] + b2.x);
                    float v3 = leaky(D[nt][3] + b2.y);
                    A[nt / 2][(nt % 2) * 2 + 0] = packh2(v0, v1);
                    A[nt / 2][(nt % 2) * 2 + 1] = packh2(v2, v3);
                }
            }

            // ---- head: 32 -> 1 via mma (only n=0 column non-zero) ----
            float Dh[4] = {0.f, 0.f, 0.f, 0.f};
            {
                uint2 b0 = s_bf[(p * TILES_PER_PRED + 24) * 32 + lane];
                uint2 b1 = s_bf[(p * TILES_PER_PRED + 25) * 32 + lane];
                uint32_t br0[2] = {b0.x, b0.y};
                uint32_t br1[2] = {b1.x, b1.y};
                mma16816(Dh, A[0], br0);
                mma16816(Dh, A[1], br1);
            }
            if (tig == 0) {
                float b3 = s_b3[p];
                ph[p][m][0] = fminf(fmaxf(Dh[0] + b3, -1.f), 1.f);   // row g
                ph[p][m][1] = fminf(fmaxf(Dh[2] + b3, -1.f), 1.f);   // row g+8
            }
        }
    }

    // ---- stats: tig==0 lanes own 4 pixels each ----
    if (tig == 0) {
#pragma unroll
        for (int m = 0; m < 2; ++m) {
#pragma unroll
            for (int hh = 0; hh < 2; ++hh) {
                int px = m * 16 + g + hh * 8;
                float x0 = s_tile[wr + 3][px + 3];
                float pa = ph[0][m][hh], pb = ph[1][m][hh], pc = ph[2][m][hh];
                float med = fmaxf(fminf(pa, fmaxf(pb, pc)), fminf(pb, pc));
                float delta = fmodf(x0 - med + 1.0f, 2.0f) - 1.0f;

                if (x0 >= -1.f && x0 <= 1.f) {
                    int idx = (int)floorf((x0 + 1.f) * 128.f);
                    idx = min(max(idx, 0), NBINS - 1);
                    atomicAdd(&s_hist[0][idx], 1u);
                }
                if (delta >= -1.f && delta <= 1.f) {
                    int idx = (int)floorf((delta + 1.f) * 128.f);
                    idx = min(max(idx, 0), NBINS - 1);
                    atomicAdd(&s_hist[1][idx], 1u);
                }
                acc_x += (double)x0 * (double)x0;
                acc_d += (double)delta * (double)delta;
            }
        }
    }

    // ---- reductions ----
#pragma unroll
    for (int o = 16; o > 0; o >>= 1) {
        acc_x += __shfl_down_sync(0xffffffffu, acc_x, o);
        acc_d += __shfl_down_sync(0xffffffffu, acc_d, o);
    }
    if (lane == 0) { s_red[0][wr] = acc_x; s_red[1][wr] = acc_d; }
    __syncthreads();
    if (tid == 0) {
        double sx = 0.0, sd = 0.0;
#pragma unroll
        for (int i = 0; i < NT / 32; ++i) { sx += s_red[0][i]; sd += s_red[1][i]; }
        atomicAdd(&g_sumsq[0], sx);
        atomicAdd(&g_sumsq[1], sd);
    }
    if (tid < NBINS) {
        unsigned c0 = s_hist[0][tid], c1 = s_hist[1][tid];
        if (c0) atomicAdd(&g_hist[0][ch][tid], c0);
        if (c1) atomicAdd(&g_hist[1][ch][tid], c1);
    }
}

__global__ void finalize_kernel(float* out) {
    __shared__ double s_ent[2][8];
    const int tid = threadIdx.x;
    double e0 = 0.0, e1 = 0.0;
    const double res = (double)(IMH * IMW);
    for (int i = tid; i < NCH * NBINS; i += 256) {
        unsigned c0 = ((const unsigned*)g_hist[0])[i];
        unsigned c1 = ((const unsigned*)g_hist[1])[i];
        if (c0) { double pp = (double)c0 / res; e0 -= pp * log2(pp); }
        if (c1) { double pp = (double)c1 / res; e1 -= pp * log2(pp); }
    }
#pragma unroll
    for (int o = 16; o > 0; o >>= 1) {
        e0 += __shfl_down_sync(0xffffffffu, e0, o);
        e1 += __shfl_down_sync(0xffffffffu, e1, o);
    }
    if ((tid & 31) == 0) { s_ent[0][tid >> 5] = e0; s_ent[1][tid >> 5] = e1; }
    __syncthreads();
    if (tid == 0) {
        double E0 = 0.0, E1 = 0.0;
#pragma unroll
        for (int i = 0; i < 8; ++i) { E0 += s_ent[0][i]; E1 += s_ent[1][i]; }
        const double N = (double)NCH * IMH * IMW;
        out[0] = (float)(255.0 * sqrt(g_sumsq[1] / N));   // loss1
        out[1] = (float)(255.0 * sqrt(g_sumsq[0] / N));   // loss0
        out[2] = (float)(E0 / (8.0 * NCH));               // invCR0
        out[3] = (float)(E1 / (8.0 * NCH));               // invCR1
    }
}

extern "C" void kernel_launch(void* const* d_in, const int* in_sizes, int n_in,
                              void* d_out, int out_size) {
    const float* x = (const float*)d_in[0];
    Params prm;
    for (int i = 0; i < 27; ++i) prm.p[i] = (const float*)d_in[1 + i];

    // launch order keeps predict_kernel at index 5 for ncu -s 5 -c 1
    pack_weights_kernel<<<4, 256>>>(prm);                 // 0
    const int per = (ZTOTAL + 3) / 4;
    for (int s = 0; s < 4; ++s)
        zero_slice_kernel<<<(per + 255) / 256, 256>>>(s); // 1-4

    dim3 grid(IMW / 32, IMH / 8, NCH);
    dim3 block(32, 8);
    predict_kernel<<<grid, block>>>(x);                   // 5
    finalize_kernel<<<1, 256>>>((float*)d_out);
}

// round 14
// speedup vs baseline: 1.5036x; 1.0819x over previous
#include <cuda_runtime.h>
#include <cuda_fp16.h>
#include <math.h>
#include <cstdint>

#define IMW 512
#define IMH 512
#define NCH 12
#define NBINS 256
#define NT 256          // 8 warps; warp w handles row gy0+w, 32 px wide

struct Params { const float* p[27]; };

__device__ double g_sumsq[2];                    // [0]=x, [1]=delta
__device__ unsigned int g_hist[2][NCH][NBINS];   // [0]=x, [1]=delta

// precomputed MMA B-fragments + biases
#define TILES_PER_PRED 26
#define NFRAG (3 * TILES_PER_PRED * 32)
__device__ uint2 g_bf[NFRAG];
__device__ float2 g_bias2[3][3][4][4];           // (b[n0], b[n0+1])
__device__ float g_b3[3];

#define ZTOTAL (2 * NCH * NBINS)
__global__ void zero_slice_kernel(int slice) {   // 4 slices
    const int per = (ZTOTAL + 3) / 4;
    int i = slice * per + blockIdx.x * blockDim.x + threadIdx.x;
    if (i < (slice + 1) * per && i < ZTOTAL) ((unsigned int*)g_hist)[i] = 0u;
    if (slice == 0 && blockIdx.x == 0 && threadIdx.x < 2) g_sumsq[threadIdx.x] = 0.0;
}

__device__ __forceinline__ uint32_t packh2(float lo, float hi) {
    __half2 h = __floats2half2_rn(lo, hi);
    return *reinterpret_cast<uint32_t*>(&h);
}

// m16n8k16 fp16 MMA, fp32 accumulate (in-place D += A*B)
__device__ __forceinline__ void mma16816(float* d, const uint32_t* a, const uint32_t* b) {
    asm volatile(
        "mma.sync.aligned.m16n8k16.row.col.f32.f16.f16.f32 "
        "{%0,%1,%2,%3}, {%4,%5,%6,%7}, {%8,%9}, {%0,%1,%2,%3};"
        : "+f"(d[0]), "+f"(d[1]), "+f"(d[2]), "+f"(d[3])
        : "r"(a[0]), "r"(a[1]), "r"(a[2]), "r"(a[3]), "r"(b[0]), "r"(b[1]));
}

// one-time fragment pack (weights -> fp16 mma B-fragment layout)
__global__ void pack_weights_kernel(Params prm) {
    const int tid = blockIdx.x * blockDim.x + threadIdx.x;
    for (int i = tid; i < NFRAG; i += gridDim.x * blockDim.x) {
        int p = i / (TILES_PER_PRED * 32);
        int rem = i % (TILES_PER_PRED * 32);
        int tile = rem / 32, ln = rem % 32;
        int ltig = ln & 3, lg = ln >> 2;
        float w[4];
        if (tile < 24) {
            int l = tile / 8, r8 = tile % 8, kt = r8 / 4, nt = r8 % 4;
            int n = nt * 8 + lg;
            int kb = kt * 16 + 2 * ltig;
            int ks[4] = {kb, kb + 1, kb + 8, kb + 9};
            if (l == 0) {
                const float* wT = prm.p[p * 9 + 0];
                const float* wL = prm.p[p * 9 + 2];
#pragma unroll
                for (int j = 0; j < 4; ++j) {
                    int k = ks[j];
                    w[j] = (k < 21) ? wT[n * 21 + k] : (k < 24 ? wL[n * 3 + (k - 21)] : 0.f);
                }
            } else {
                const float* wm = prm.p[p * 9 + (l == 1 ? 3 : 5)];
#pragma unroll
                for (int j = 0; j < 4; ++j) w[j] = wm[n * 32 + ks[j]];
            }
        } else {
            int kt = tile - 24;
            const float* w3 = prm.p[p * 9 + 7];
            int kb = kt * 16 + 2 * ltig;
#pragma unroll
            for (int j = 0; j < 4; ++j) {
                int k = kb + (j & 1) + (j >> 1) * 8;
                w[j] = (lg == 0) ? w3[k] : 0.f;
            }
        }
        uint2 v;
        v.x = packh2(w[0], w[1]);
        v.y = packh2(w[2], w[3]);
        g_bf[i] = v;
    }
    // biases
    for (int i = tid; i < 3 * 3 * 16; i += gridDim.x * blockDim.x) {
        int p = i / 48, r = i % 48, l = r / 16, q = r % 16;
        int nt = q / 4, tg = q % 4;
        const float* b = prm.p[p * 9 + (l == 0 ? 1 : (l == 1 ? 4 : 6))];
        int n0 = nt * 8 + 2 * tg;
        g_bias2[p][l][nt][tg] = make_float2(b[n0], b[n0 + 1]);
    }
    if (tid < 3) g_b3[tid] = prm.p[tid * 9 + 8][0];
}

__global__ __launch_bounds__(NT) void predict_kernel(const float* __restrict__ x) {
    __shared__ __align__(16) uint2 s_bf[NFRAG];     // 19.5 KB
    __shared__ float s_tile[11][40];                // 8 rows + 3 halo, 32 cols + 6 halo (38 used)
    __shared__ float2 s_bias2[3][3][4][4];
    __shared__ float s_b3[3];
    __shared__ unsigned int s_hist[2][NBINS];
    __shared__ double s_red[2][NT / 32];

    const int lane = threadIdx.x;
    const int wr   = threadIdx.y;       // warp row (0..7)
    const int tid  = wr * 32 + lane;
    const int tig  = lane & 3;          // thread-in-group
    const int g    = lane >> 2;         // group id (row base)
    const int ch   = blockIdx.z;
    const int gx0  = blockIdx.x * 32;
    const int gy0  = blockIdx.y * 8;

    for (int i = tid; i < 2 * NBINS; i += NT) ((unsigned int*)s_hist)[i] = 0u;

    // coalesced fragment copy (uint4: 2 fragments per load)
    {
        const uint4* src = (const uint4*)g_bf;
        uint4* dst = (uint4*)s_bf;
#pragma unroll
        for (int j = 0; j < NFRAG / 2 / NT + 1; ++j) {
            int i = j * NT + tid;
            if (i < NFRAG / 2) dst[i] = src[i];
        }
    }
    for (int i = tid; i < 3 * 3 * 16; i += NT) ((float2*)s_bias2)[i] = ((const float2*)g_bias2)[i];
    if (tid < 3) s_b3[tid] = g_b3[tid];

    // ---- stage input tile with halo (top 3 rows, left/right 3 cols) ----
    const float* xch = x + (size_t)ch * IMH * IMW;
    for (int i = tid; i < 11 * 38; i += NT) {
        int r = i / 38, c = i % 38;
        int gr = gy0 - 3 + r, gc = gx0 - 3 + c;
        float v = 0.f;
        if (gr >= 0 && gc >= 0 && gc < IMW) v = xch[gr * IMW + gc];
        s_tile[r][c] = v;
    }
    __syncthreads();

    // ---- hoisted tap offsets (6 per thread, px-independent) ----
    const float* st = &s_tile[0][0];
    int toff[6];
    {
        int ks[6] = {2 * tig, 2 * tig + 1, 2 * tig + 8, 2 * tig + 9,
                     16 + 2 * tig, 16 + 2 * tig + 1};
#pragma unroll
        for (int i = 0; i < 6; ++i) {
            int k = ks[i];
            toff[i] = (k < 21) ? (wr + k / 7) * 40 + (k % 7)
                               : (wr + 3) * 40 + (k - 21);
        }
    }

    const __half2 C001 = __float2half2_rn(0.01f);
    float ph[3][2][2];   // [pred][mtile][rowhalf], valid at tig==0
    double acc_x = 0.0, acc_d = 0.0;

#pragma unroll 1
    for (int m = 0; m < 2; ++m) {
        const int px0 = m * 16 + g;        // row g
        const int px1 = px0 + 8;           // row g+8

        // ---- build layer-0 A fragments from hoisted offsets ----
        uint32_t A0[2][4];
        A0[0][0] = packh2(st[toff[0] + px0], st[toff[1] + px0]);
        A0[0][1] = packh2(st[toff[0] + px1], st[toff[1] + px1]);
        A0[0][2] = packh2(st[toff[2] + px0], st[toff[3] + px0]);
        A0[0][3] = packh2(st[toff[2] + px1], st[toff[3] + px1]);
        A0[1][0] = packh2(st[toff[4] + px0], st[toff[5] + px0]);
        A0[1][1] = packh2(st[toff[4] + px1], st[toff[5] + px1]);
        A0[1][2] = 0u;   // k >= 24 taps are zero
        A0[1][3] = 0u;

#pragma unroll 1
        for (int p = 0; p < 3; ++p) {
            uint32_t A[2][4];
#pragma unroll
            for (int kt = 0; kt < 2; ++kt)
#pragma unroll
                for (int j = 0; j < 4; ++j) A[kt][j] = A0[kt][j];

            // ---- layers 0,1,2 ----
#pragma unroll
            for (int l = 0; l < 3; ++l) {
                // D initialized with bias (MMA accumulates on top)
                float D[4][4];
#pragma unroll
                for (int nt = 0; nt < 4; ++nt) {
                    float2 b2 = s_bias2[p][l][nt][tig];
                    D[nt][0] = b2.x; D[nt][1] = b2.y;
                    D[nt][2] = b2.x; D[nt][3] = b2.y;
                }

#pragma unroll
                for (int kt = 0; kt < 2; ++kt) {
#pragma unroll
                    for (int nt = 0; nt < 4; ++nt) {
                        uint2 bv = s_bf[(p * TILES_PER_PRED + l * 8 + kt * 4 + nt) * 32 + lane];
                        uint32_t br[2] = {bv.x, bv.y};
                        mma16816(D[nt], A[kt], br);
                    }
                }
                // fp16x2 epilogue: cvt pairs, leaky in half2, store as next A
#pragma unroll
                for (int nt = 0; nt < 4; ++nt) {
                    __half2 h01 = __floats2half2_rn(D[nt][0], D[nt][1]);
                    __half2 h23 = __floats2half2_rn(D[nt][2], D[nt][3]);
                    h01 = __hmax2(h01, __hmul2(h01, C001));
                    h23 = __hmax2(h23, __hmul2(h23, C001));
                    A[nt / 2][(nt % 2) * 2 + 0] = *reinterpret_cast<uint32_t*>(&h01);
                    A[nt / 2][(nt % 2) * 2 + 1] = *reinterpret_cast<uint32_t*>(&h23);
                }
            }

            // ---- head: 32 -> 1 via mma (bias in D init) ----
            float b3 = s_b3[p];
            float Dh[4] = {b3, 0.f, b3, 0.f};
            {
                uint2 b0 = s_bf[(p * TILES_PER_PRED + 24) * 32 + lane];
                uint2 b1 = s_bf[(p * TILES_PER_PRED + 25) * 32 + lane];
                uint32_t br0[2] = {b0.x, b0.y};
                uint32_t br1[2] = {b1.x, b1.y};
                mma16816(Dh, A[0], br0);
                mma16816(Dh, A[1], br1);
            }
            if (tig == 0) {
                ph[p][m][0] = fminf(fmaxf(Dh[0], -1.f), 1.f);   // row g
                ph[p][m][1] = fminf(fmaxf(Dh[2], -1.f), 1.f);   // row g+8
            }
        }
    }

    // ---- stats: tig==0 lanes own 4 pixels each ----
    if (tig == 0) {
#pragma unroll
        for (int m = 0; m < 2; ++m) {
#pragma unroll
            for (int hh = 0; hh < 2; ++hh) {
                int px = m * 16 + g + hh * 8;
                float x0 = s_tile[wr + 3][px + 3];
                float pa = ph[0][m][hh], pb = ph[1][m][hh], pc = ph[2][m][hh];
                float med = fmaxf(fminf(pa, fmaxf(pb, pc)), fminf(pb, pc));
                float delta = fmodf(x0 - med + 1.0f, 2.0f) - 1.0f;

                if (x0 >= -1.f && x0 <= 1.f) {
                    int idx = (int)floorf((x0 + 1.f) * 128.f);
                    idx = min(max(idx, 0), NBINS - 1);
                    atomicAdd(&s_hist[0][idx], 1u);
                }
                if (delta >= -1.f && delta <= 1.f) {
                    int idx = (int)floorf((delta + 1.f) * 128.f);
                    idx = min(max(idx, 0), NBINS - 1);
                    atomicAdd(&s_hist[1][idx], 1u);
                }
                acc_x += (double)x0 * (double)x0;
                acc_d += (double)delta * (double)delta;
            }
        }
    }

    // ---- reductions ----
#pragma unroll
    for (int o = 16; o > 0; o >>= 1) {
        acc_x += __shfl_down_sync(0xffffffffu, acc_x, o);
        acc_d += __shfl_down_sync(0xffffffffu, acc_d, o);
    }
    if (lane == 0) { s_red[0][wr] = acc_x; s_red[1][wr] = acc_d; }
    __syncthreads();
    if (tid == 0) {
        double sx = 0.0, sd = 0.0;
#pragma unroll
        for (int i = 0; i < NT / 32; ++i) { sx += s_red[0][i]; sd += s_red[1][i]; }
        atomicAdd(&g_sumsq[0], sx);
        atomicAdd(&g_sumsq[1], sd);
    }
    if (tid < NBINS) {
        unsigned c0 = s_hist[0][tid], c1 = s_hist[1][tid];
        if (c0) atomicAdd(&g_hist[0][ch][tid], c0);
        if (c1) atomicAdd(&g_hist[1][ch][tid], c1);
    }
}

__global__ void finalize_kernel(float* out) {
    __shared__ double s_ent[2][8];
    const int tid = threadIdx.x;
    double e0 = 0.0, e1 = 0.0;
    const double res = (double)(IMH * IMW);
    for (int i = tid; i < NCH * NBINS; i += 256) {
        unsigned c0 = ((const unsigned*)g_hist[0])[i];
        unsigned c1 = ((const unsigned*)g_hist[1])[i];
        if (c0) { double pp = (double)c0 / res; e0 -= pp * log2(pp); }
        if (c1) { double pp = (double)c1 / res; e1 -= pp * log2(pp); }
    }
#pragma unroll
    for (int o = 16; o > 0; o >>= 1) {
        e0 += __shfl_down_sync(0xffffffffu, e0, o);
        e1 += __shfl_down_sync(0xffffffffu, e1, o);
    }
    if ((tid & 31) == 0) { s_ent[0][tid >> 5] = e0; s_ent[1][tid >> 5] = e1; }
    __syncthreads();
    if (tid == 0) {
        double E0 = 0.0, E1 = 0.0;
#pragma unroll
        for (int i = 0; i < 8; ++i) { E0 += s_ent[0][i]; E1 += s_ent[1][i]; }
        const double N = (double)NCH * IMH * IMW;
        out[0] = (float)(255.0 * sqrt(g_sumsq[1] / N));   // loss1
        out[1] = (float)(255.0 * sqrt(g_sumsq[0] / N));   // loss0
        out[2] = (float)(E0 / (8.0 * NCH));               // invCR0
        out[3] = (float)(E1 / (8.0 * NCH));               // invCR1
    }
}

extern "C" void kernel_launch(void* const* d_in, const int* in_sizes, int n_in,
                              void* d_out, int out_size) {
    const float* x = (const float*)d_in[0];
    Params prm;
    for (int i = 0; i < 27; ++i) prm.p[i] = (const float*)d_in[1 + i];

    // launch order keeps predict_kernel at index 5 for ncu -s 5 -c 1
    pack_weights_kernel<<<4, 256>>>(prm);                 // 0
    const int per = (ZTOTAL + 3) / 4;
    for (int s = 0; s < 4; ++s)
        zero_slice_kernel<<<(per + 255) / 256, 256>>>(s); // 1-4

    dim3 grid(IMW / 32, IMH / 8, NCH);
    dim3 block(32, 8);
    predict_kernel<<<grid, block>>>(x);                   // 5
    finalize_kernel<<<1, 256>>>((float*)d_out);
}

// round 16
// speedup vs baseline: 1.6309x; 1.0847x over previous
#include <cuda_runtime.h>
#include <cuda_fp16.h>
#include <math.h>
#include <cstdint>

#define IMW 512
#define IMH 512
#define NCH 12
#define NBINS 256
#define NT 256          // 8 warps; warp w handles row gy0+w, 32 px wide

struct Params { const float* p[27]; };

__device__ double g_sumsq[2];                    // [0]=x, [1]=delta
__device__ unsigned int g_hist[2][NCH][NBINS];   // [0]=x, [1]=delta

// precomputed MMA B-fragments + biases
#define TILES_PER_PRED 26
#define NFRAG (3 * TILES_PER_PRED * 32)
__device__ uint2 g_bf[NFRAG];
__device__ uint32_t g_biash[3][3][4][4];         // half2 (b[n0], b[n0+1])
__device__ float g_b3[3];

#define ZTOTAL (2 * NCH * NBINS)
__global__ void zero_slice_kernel(int slice) {   // 4 slices
    const int per = (ZTOTAL + 3) / 4;
    int i = slice * per + blockIdx.x * blockDim.x + threadIdx.x;
    if (i < (slice + 1) * per && i < ZTOTAL) ((unsigned int*)g_hist)[i] = 0u;
    if (slice == 0 && blockIdx.x == 0 && threadIdx.x < 2) g_sumsq[threadIdx.x] = 0.0;
}

__device__ __forceinline__ uint32_t packh2(float lo, float hi) {
    __half2 h = __floats2half2_rn(lo, hi);
    return *reinterpret_cast<uint32_t*>(&h);
}
__device__ __forceinline__ __half2 u2h(uint32_t u) { return *reinterpret_cast<__half2*>(&u); }
__device__ __forceinline__ uint32_t h2u(__half2 h) { return *reinterpret_cast<uint32_t*>(&h); }

// m16n8k16 fp16 MMA, fp16 accumulate (in-place D += A*B); D = 2 packed half2 regs
__device__ __forceinline__ void mma16816h(uint32_t* d, const uint32_t* a, const uint32_t* b) {
    asm volatile(
        "mma.sync.aligned.m16n8k16.row.col.f16.f16.f16.f16 "
        "{%0,%1}, {%2,%3,%4,%5}, {%6,%7}, {%0,%1};"
        : "+r"(d[0]), "+r"(d[1])
        : "r"(a[0]), "r"(a[1]), "r"(a[2]), "r"(a[3]), "r"(b[0]), "r"(b[1]));
}

// one-time fragment pack (weights -> fp16 mma B-fragment layout)
__global__ void pack_weights_kernel(Params prm) {
    const int tid = blockIdx.x * blockDim.x + threadIdx.x;
    for (int i = tid; i < NFRAG; i += gridDim.x * blockDim.x) {
        int p = i / (TILES_PER_PRED * 32);
        int rem = i % (TILES_PER_PRED * 32);
        int tile = rem / 32, ln = rem % 32;
        int ltig = ln & 3, lg = ln >> 2;
        float w[4];
        if (tile < 24) {
            int l = tile / 8, r8 = tile % 8, kt = r8 / 4, nt = r8 % 4;
            int n = nt * 8 + lg;
            int kb = kt * 16 + 2 * ltig;
            int ks[4] = {kb, kb + 1, kb + 8, kb + 9};
            if (l == 0) {
                const float* wT = prm.p[p * 9 + 0];
                const float* wL = prm.p[p * 9 + 2];
#pragma unroll
                for (int j = 0; j < 4; ++j) {
                    int k = ks[j];
                    w[j] = (k < 21) ? wT[n * 21 + k] : (k < 24 ? wL[n * 3 + (k - 21)] : 0.f);
                }
            } else {
                const float* wm = prm.p[p * 9 + (l == 1 ? 3 : 5)];
#pragma unroll
                for (int j = 0; j < 4; ++j) w[j] = wm[n * 32 + ks[j]];
            }
        } else {
            int kt = tile - 24;
            const float* w3 = prm.p[p * 9 + 7];
            int kb = kt * 16 + 2 * ltig;
#pragma unroll
            for (int j = 0; j < 4; ++j) {
                int k = kb + (j & 1) + (j >> 1) * 8;
                w[j] = (lg == 0) ? w3[k] : 0.f;
            }
        }
        uint2 v;
        v.x = packh2(w[0], w[1]);
        v.y = packh2(w[2], w[3]);
        g_bf[i] = v;
    }
    // biases (half2)
    for (int i = tid; i < 3 * 3 * 16; i += gridDim.x * blockDim.x) {
        int p = i / 48, r = i % 48, l = r / 16, q = r % 16;
        int nt = q / 4, tg = q % 4;
        const float* b = prm.p[p * 9 + (l == 0 ? 1 : (l == 1 ? 4 : 6))];
        int n0 = nt * 8 + 2 * tg;
        g_biash[p][l][nt][tg] = packh2(b[n0], b[n0 + 1]);
    }
    if (tid < 3) g_b3[tid] = prm.p[tid * 9 + 8][0];
}

__global__ __launch_bounds__(NT) void predict_kernel(const float* __restrict__ x) {
    __shared__ __align__(16) uint2 s_bf[NFRAG];     // 19.5 KB
    __shared__ float s_tile[11][40];                // 8 rows + 3 halo, 32 cols + 6 halo (38 used)
    __shared__ uint32_t s_biash[3][3][4][4];
    __shared__ float s_b3[3];
    __shared__ unsigned int s_hist[2][NBINS];
    __shared__ double s_red[2][NT / 32];

    const int lane = threadIdx.x;
    const int wr   = threadIdx.y;       // warp row (0..7)
    const int tid  = wr * 32 + lane;
    const int tig  = lane & 3;          // thread-in-group
    const int g    = lane >> 2;         // group id (row base)
    const int ch   = blockIdx.z;
    const int gx0  = blockIdx.x * 32;
    const int gy0  = blockIdx.y * 8;

    for (int i = tid; i < 2 * NBINS; i += NT) ((unsigned int*)s_hist)[i] = 0u;

    // coalesced fragment copy (uint4: 2 fragments per load)
    {
        const uint4* src = (const uint4*)g_bf;
        uint4* dst = (uint4*)s_bf;
#pragma unroll
        for (int j = 0; j < NFRAG / 2 / NT + 1; ++j) {
            int i = j * NT + tid;
            if (i < NFRAG / 2) dst[i] = src[i];
        }
    }
    for (int i = tid; i < 3 * 3 * 16; i += NT) ((uint32_t*)s_biash)[i] = ((const uint32_t*)g_biash)[i];
    if (tid < 3) s_b3[tid] = g_b3[tid];

    // ---- stage input tile with halo (top 3 rows, left/right 3 cols) ----
    const float* xch = x + (size_t)ch * IMH * IMW;
    for (int i = tid; i < 11 * 38; i += NT) {
        int r = i / 38, c = i % 38;
        int gr = gy0 - 3 + r, gc = gx0 - 3 + c;
        float v = 0.f;
        if (gr >= 0 && gc >= 0 && gc < IMW) v = xch[gr * IMW + gc];
        s_tile[r][c] = v;
    }
    __syncthreads();

    // ---- hoisted tap offsets (6 per thread, px-independent) ----
    const float* st = &s_tile[0][0];
    int toff[6];
    {
        int ks[6] = {2 * tig, 2 * tig + 1, 2 * tig + 8, 2 * tig + 9,
                     16 + 2 * tig, 16 + 2 * tig + 1};
#pragma unroll
        for (int i = 0; i < 6; ++i) {
            int k = ks[i];
            toff[i] = (k < 21) ? (wr + k / 7) * 40 + (k % 7)
                               : (wr + 3) * 40 + (k - 21);
        }
    }

    const __half2 C001 = __float2half2_rn(0.01f);
    float ph[3][2][2];   // [pred][mtile][rowhalf], valid at tig==0
    double acc_x = 0.0, acc_d = 0.0;

#pragma unroll 1
    for (int m = 0; m < 2; ++m) {
        const int px0 = m * 16 + g;        // row g
        const int px1 = px0 + 8;           // row g+8

        // ---- build layer-0 A fragments from hoisted offsets ----
        uint32_t A0[2][4];
        A0[0][0] = packh2(st[toff[0] + px0], st[toff[1] + px0]);
        A0[0][1] = packh2(st[toff[0] + px1], st[toff[1] + px1]);
        A0[0][2] = packh2(st[toff[2] + px0], st[toff[3] + px0]);
        A0[0][3] = packh2(st[toff[2] + px1], st[toff[3] + px1]);
        A0[1][0] = packh2(st[toff[4] + px0], st[toff[5] + px0]);
        A0[1][1] = packh2(st[toff[4] + px1], st[toff[5] + px1]);
        A0[1][2] = 0u;   // k >= 24 taps are zero
        A0[1][3] = 0u;

#pragma unroll 1
        for (int p = 0; p < 3; ++p) {
            uint32_t A[2][4];
#pragma unroll
            for (int kt = 0; kt < 2; ++kt)
#pragma unroll
                for (int j = 0; j < 4; ++j) A[kt][j] = A0[kt][j];

            // ---- layers 0,1,2 (fp16 accumulate; D regs ARE the next A slots) ----
#pragma unroll
            for (int l = 0; l < 3; ++l) {
                uint32_t D[4][2];
#pragma unroll
                for (int nt = 0; nt < 4; ++nt) {
                    uint32_t b2 = s_biash[p][l][nt][tig];
                    D[nt][0] = b2;
                    D[nt][1] = b2;
                }

#pragma unroll
                for (int kt = 0; kt < 2; ++kt) {
#pragma unroll
                    for (int nt = 0; nt < 4; ++nt) {
                        uint2 bv = s_bf[(p * TILES_PER_PRED + l * 8 + kt * 4 + nt) * 32 + lane];
                        uint32_t br[2] = {bv.x, bv.y};
                        mma16816h(D[nt], A[kt], br);
                    }
                }
                // epilogue: leaky in half2, D -> next A directly
#pragma unroll
                for (int nt = 0; nt < 4; ++nt) {
                    __half2 h0 = u2h(D[nt][0]);
                    __half2 h1 = u2h(D[nt][1]);
                    h0 = __hmax2(h0, __hmul2(h0, C001));
                    h1 = __hmax2(h1, __hmul2(h1, C001));
                    A[nt / 2][(nt % 2) * 2 + 0] = h2u(h0);
                    A[nt / 2][(nt % 2) * 2 + 1] = h2u(h1);
                }
            }

            // ---- head: 32 -> 1 via mma (bias in D init, col 0) ----
            uint32_t Dh[2];
            Dh[0] = packh2(s_b3[p], 0.f);
            Dh[1] = Dh[0];
            {
                uint2 b0 = s_bf[(p * TILES_PER_PRED + 24) * 32 + lane];
                uint2 b1 = s_bf[(p * TILES_PER_PRED + 25) * 32 + lane];
                uint32_t br0[2] = {b0.x, b0.y};
                uint32_t br1[2] = {b1.x, b1.y};
                mma16816h(Dh, A[0], br0);
                mma16816h(Dh, A[1], br1);
            }
            if (tig == 0) {
                ph[p][m][0] = fminf(fmaxf(__low2float(u2h(Dh[0])), -1.f), 1.f);   // row g
                ph[p][m][1] = fminf(fmaxf(__low2float(u2h(Dh[1])), -1.f), 1.f);   // row g+8
            }
        }
    }

    // ---- stats: tig==0 lanes own 4 pixels each ----
    if (tig == 0) {
#pragma unroll
        for (int m = 0; m < 2; ++m) {
#pragma unroll
            for (int hh = 0; hh < 2; ++hh) {
                int px = m * 16 + g + hh * 8;
                float x0 = s_tile[wr + 3][px + 3];
                float pa = ph[0][m][hh], pb = ph[1][m][hh], pc = ph[2][m][hh];
                float med = fmaxf(fminf(pa, fmaxf(pb, pc)), fminf(pb, pc));
                float delta = fmodf(x0 - med + 1.0f, 2.0f) - 1.0f;

                if (x0 >= -1.f && x0 <= 1.f) {
                    int idx = (int)floorf((x0 + 1.f) * 128.f);
                    idx = min(max(idx, 0), NBINS - 1);
                    atomicAdd(&s_hist[0][idx], 1u);
                }
                if (delta >= -1.f && delta <= 1.f) {
                    int idx = (int)floorf((delta + 1.f) * 128.f);
                    idx = min(max(idx, 0), NBINS - 1);
                    atomicAdd(&s_hist[1][idx], 1u);
                }
                acc_x += (double)x0 * (double)x0;
                acc_d += (double)delta * (double)delta;
            }
        }
    }

    // ---- reductions ----
#pragma unroll
    for (int o = 16; o > 0; o >>= 1) {
        acc_x += __shfl_down_sync(0xffffffffu, acc_x, o);
        acc_d += __shfl_down_sync(0xffffffffu, acc_d, o);
    }
    if (lane == 0) { s_red[0][wr] = acc_x; s_red[1][wr] = acc_d; }
    __syncthreads();
    if (tid == 0) {
        double sx = 0.0, sd = 0.0;
#pragma unroll
        for (int i = 0; i < NT / 32; ++i) { sx += s_red[0][i]; sd += s_red[1][i]; }
        atomicAdd(&g_sumsq[0], sx);
        atomicAdd(&g_sumsq[1], sd);
    }
    if (tid < NBINS) {
        unsigned c0 = s_hist[0][tid], c1 = s_hist[1][tid];
        if (c0) atomicAdd(&g_hist[0][ch][tid], c0);
        if (c1) atomicAdd(&g_hist[1][ch][tid], c1);
    }
}

__global__ void finalize_kernel(float* out) {
    __shared__ double s_ent[2][8];
    const int tid = threadIdx.x;
    double e0 = 0.0, e1 = 0.0;
    const double res = (double)(IMH * IMW);
    for (int i = tid; i < NCH * NBINS; i += 256) {
        unsigned c0 = ((const unsigned*)g_hist[0])[i];
        unsigned c1 = ((const unsigned*)g_hist[1])[i];
        if (c0) { double pp = (double)c0 / res; e0 -= pp * log2(pp); }
        if (c1) { double pp = (double)c1 / res; e1 -= pp * log2(pp); }
    }
#pragma unroll
    for (int o = 16; o > 0; o >>= 1) {
        e0 += __shfl_down_sync(0xffffffffu, e0, o);
        e1 += __shfl_down_sync(0xffffffffu, e1, o);
    }
    if ((tid & 31) == 0) { s_ent[0][tid >> 5] = e0; s_ent[1][tid >> 5] = e1; }
    __syncthreads();
    if (tid == 0) {
        double E0 = 0.0, E1 = 0.0;
#pragma unroll
        for (int i = 0; i < 8; ++i) { E0 += s_ent[0][i]; E1 += s_ent[1][i]; }
        const double N = (double)NCH * IMH * IMW;
        out[0] = (float)(255.0 * sqrt(g_sumsq[1] / N));   // loss1
        out[1] = (float)(255.0 * sqrt(g_sumsq[0] / N));   // loss0
        out[2] = (float)(E0 / (8.0 * NCH));               // invCR0
        out[3] = (float)(E1 / (8.0 * NCH));               // invCR1
    }
}

extern "C" void kernel_launch(void* const* d_in, const int* in_sizes, int n_in,
                              void* d_out, int out_size) {
    const float* x = (const float*)d_in[0];
    Params prm;
    for (int i = 0; i < 27; ++i) prm.p[i] = (const float*)d_in[1 + i];

    // launch order keeps predict_kernel at index 5 for ncu -s 5 -c 1
    pack_weights_kernel<<<4, 256>>>(prm);                 // 0
    const int per = (ZTOTAL + 3) / 4;
    for (int s = 0; s < 4; ++s)
        zero_slice_kernel<<<(per + 255) / 256, 256>>>(s); // 1-4

    dim3 grid(IMW / 32, IMH / 8, NCH);
    dim3 block(32, 8);
    predict_kernel<<<grid, block>>>(x);                   // 5
    finalize_kernel<<<1, 256>>>((float*)d_out);
}

// round 17
// speedup vs baseline: 1.6561x; 1.0155x over previous
#include <cuda_runtime.h>
#include <cuda_fp16.h>
#include <math.h>
#include <cstdint>

#define IMW 512
#define IMH 512
#define NCH 12
#define NBINS 256
#define NT 256          // 8 warps; warp w handles row gy0+w, 32 px wide

struct Params { const float* p[27]; };

__device__ double g_sumsq[2];                    // [0]=x, [1]=delta
__device__ unsigned int g_hist[2][NCH][NBINS];   // [0]=x, [1]=delta

// precomputed MMA B-fragments + biases
#define TILES_PER_PRED 26
#define NFRAG (3 * TILES_PER_PRED * 32)
__device__ uint2 g_bf[NFRAG];
__device__ uint32_t g_biash[3][3][4][4];         // half2 (b[n0], b[n0+1])
__device__ float g_b3[3];

#define ZTOTAL (2 * NCH * NBINS)
__global__ void zero_slice_kernel(int slice) {   // 4 slices
    const int per = (ZTOTAL + 3) / 4;
    int i = slice * per + blockIdx.x * blockDim.x + threadIdx.x;
    if (i < (slice + 1) * per && i < ZTOTAL) ((unsigned int*)g_hist)[i] = 0u;
    if (slice == 0 && blockIdx.x == 0 && threadIdx.x < 2) g_sumsq[threadIdx.x] = 0.0;
}

__device__ __forceinline__ uint32_t packh2(float lo, float hi) {
    __half2 h = __floats2half2_rn(lo, hi);
    return *reinterpret_cast<uint32_t*>(&h);
}
__device__ __forceinline__ __half2 u2h(uint32_t u) { return *reinterpret_cast<__half2*>(&u); }
__device__ __forceinline__ uint32_t h2u(__half2 h) { return *reinterpret_cast<uint32_t*>(&h); }

// m16n8k16 fp16 MMA, fp16 accumulate (in-place D += A*B); D = 2 packed half2 regs
__device__ __forceinline__ void mma16816h(uint32_t* d, const uint32_t* a, const uint32_t* b) {
    asm volatile(
        "mma.sync.aligned.m16n8k16.row.col.f16.f16.f16.f16 "
        "{%0,%1}, {%2,%3,%4,%5}, {%6,%7}, {%0,%1};"
        : "+r"(d[0]), "+r"(d[1])
        : "r"(a[0]), "r"(a[1]), "r"(a[2]), "r"(a[3]), "r"(b[0]), "r"(b[1]));
}

// one-time fragment pack (weights -> fp16 mma B-fragment layout)
__global__ void pack_weights_kernel(Params prm) {
    const int tid = blockIdx.x * blockDim.x + threadIdx.x;
    for (int i = tid; i < NFRAG; i += gridDim.x * blockDim.x) {
        int p = i / (TILES_PER_PRED * 32);
        int rem = i % (TILES_PER_PRED * 32);
        int tile = rem / 32, ln = rem % 32;
        int ltig = ln & 3, lg = ln >> 2;
        float w[4];
        if (tile < 24) {
            int l = tile / 8, r8 = tile % 8, kt = r8 / 4, nt = r8 % 4;
            int n = nt * 8 + lg;
            int kb = kt * 16 + 2 * ltig;
            int ks[4] = {kb, kb + 1, kb + 8, kb + 9};
            if (l == 0) {
                const float* wT = prm.p[p * 9 + 0];
                const float* wL = prm.p[p * 9 + 2];
#pragma unroll
                for (int j = 0; j < 4; ++j) {
                    int k = ks[j];
                    w[j] = (k < 21) ? wT[n * 21 + k] : (k < 24 ? wL[n * 3 + (k - 21)] : 0.f);
                }
            } else {
                const float* wm = prm.p[p * 9 + (l == 1 ? 3 : 5)];
#pragma unroll
                for (int j = 0; j < 4; ++j) w[j] = wm[n * 32 + ks[j]];
            }
        } else {
            int kt = tile - 24;
            const float* w3 = prm.p[p * 9 + 7];
            int kb = kt * 16 + 2 * ltig;
#pragma unroll
            for (int j = 0; j < 4; ++j) {
                int k = kb + (j & 1) + (j >> 1) * 8;
                w[j] = (lg == 0) ? w3[k] : 0.f;
            }
        }
        uint2 v;
        v.x = packh2(w[0], w[1]);
        v.y = packh2(w[2], w[3]);
        g_bf[i] = v;
    }
    // biases (half2)
    for (int i = tid; i < 3 * 3 * 16; i += gridDim.x * blockDim.x) {
        int p = i / 48, r = i % 48, l = r / 16, q = r % 16;
        int nt = q / 4, tg = q % 4;
        const float* b = prm.p[p * 9 + (l == 0 ? 1 : (l == 1 ? 4 : 6))];
        int n0 = nt * 8 + 2 * tg;
        g_biash[p][l][nt][tg] = packh2(b[n0], b[n0 + 1]);
    }
    if (tid < 3) g_b3[tid] = prm.p[tid * 9 + 8][0];
}

__global__ __launch_bounds__(NT) void predict_kernel(const float* __restrict__ x) {
    __shared__ __align__(16) uint2 s_bf[NFRAG];     // 19.5 KB
    __shared__ float s_tile[11][40];                // 8 rows + 3 halo, 32 cols + 6 halo (38 used)
    __shared__ uint32_t s_biash[3][3][4][4];
    __shared__ float s_b3[3];
    __shared__ unsigned int s_hist[2][NBINS];
    __shared__ double s_red[2][NT / 32];

    const int lane = threadIdx.x;
    const int wr   = threadIdx.y;       // warp row (0..7)
    const int tid  = wr * 32 + lane;
    const int tig  = lane & 3;          // thread-in-group
    const int g    = lane >> 2;         // group id (row base)
    const int ch   = blockIdx.z;
    const int gx0  = blockIdx.x * 32;
    const int gy0  = blockIdx.y * 8;

    for (int i = tid; i < 2 * NBINS; i += NT) ((unsigned int*)s_hist)[i] = 0u;

    // coalesced fragment copy (uint4: 2 fragments per load)
    {
        const uint4* src = (const uint4*)g_bf;
        uint4* dst = (uint4*)s_bf;
#pragma unroll
        for (int j = 0; j < NFRAG / 2 / NT + 1; ++j) {
            int i = j * NT + tid;
            if (i < NFRAG / 2) dst[i] = src[i];
        }
    }
    for (int i = tid; i < 3 * 3 * 16; i += NT) ((uint32_t*)s_biash)[i] = ((const uint32_t*)g_biash)[i];
    if (tid < 3) s_b3[tid] = g_b3[tid];

    // ---- stage input tile with halo (top 3 rows, left/right 3 cols) ----
    const float* xch = x + (size_t)ch * IMH * IMW;
    for (int i = tid; i < 11 * 38; i += NT) {
        int r = i / 38, c = i % 38;
        int gr = gy0 - 3 + r, gc = gx0 - 3 + c;
        float v = 0.f;
        if (gr >= 0 && gc >= 0 && gc < IMW) v = xch[gr * IMW + gc];
        s_tile[r][c] = v;
    }
    __syncthreads();

    // ---- hoisted tap offsets (6 per thread, px-independent) ----
    const float* st = &s_tile[0][0];
    int toff[6];
    {
        int ks[6] = {2 * tig, 2 * tig + 1, 2 * tig + 8, 2 * tig + 9,
                     16 + 2 * tig, 16 + 2 * tig + 1};
#pragma unroll
        for (int i = 0; i < 6; ++i) {
            int k = ks[i];
            toff[i] = (k < 21) ? (wr + k / 7) * 40 + (k % 7)
                               : (wr + 3) * 40 + (k - 21);
        }
    }

    const __half2 C001 = __float2half2_rn(0.01f);
    float ph[3][2][2];   // [pred][mtile][rowhalf], valid at tig==0
    double acc_x = 0.0, acc_d = 0.0;

#pragma unroll 1
    for (int m = 0; m < 2; ++m) {
        const int px0 = m * 16 + g;        // row g
        const int px1 = px0 + 8;           // row g+8

        // ---- build layer-0 A fragments from hoisted offsets ----
        uint32_t A0[2][4];
        A0[0][0] = packh2(st[toff[0] + px0], st[toff[1] + px0]);
        A0[0][1] = packh2(st[toff[0] + px1], st[toff[1] + px1]);
        A0[0][2] = packh2(st[toff[2] + px0], st[toff[3] + px0]);
        A0[0][3] = packh2(st[toff[2] + px1], st[toff[3] + px1]);
        A0[1][0] = packh2(st[toff[4] + px0], st[toff[5] + px0]);
        A0[1][1] = packh2(st[toff[4] + px1], st[toff[5] + px1]);
        A0[1][2] = 0u;   // k >= 24 taps are zero
        A0[1][3] = 0u;

        // ---- all 3 predictors unrolled: 3 independent MMA chains interleaved ----
#pragma unroll
        for (int p = 0; p < 3; ++p) {
            uint32_t A[2][4];
#pragma unroll
            for (int kt = 0; kt < 2; ++kt)
#pragma unroll
                for (int j = 0; j < 4; ++j) A[kt][j] = A0[kt][j];

            // ---- layers 0,1,2 (fp16 accumulate; D regs ARE the next A slots) ----
#pragma unroll
            for (int l = 0; l < 3; ++l) {
                uint32_t D[4][2];
#pragma unroll
                for (int nt = 0; nt < 4; ++nt) {
                    uint32_t b2 = s_biash[p][l][nt][tig];
                    D[nt][0] = b2;
                    D[nt][1] = b2;
                }

#pragma unroll
                for (int kt = 0; kt < 2; ++kt) {
#pragma unroll
                    for (int nt = 0; nt < 4; ++nt) {
                        uint2 bv = s_bf[(p * TILES_PER_PRED + l * 8 + kt * 4 + nt) * 32 + lane];
                        uint32_t br[2] = {bv.x, bv.y};
                        mma16816h(D[nt], A[kt], br);
                    }
                }
                // epilogue: leaky in half2, D -> next A directly
#pragma unroll
                for (int nt = 0; nt < 4; ++nt) {
                    __half2 h0 = u2h(D[nt][0]);
                    __half2 h1 = u2h(D[nt][1]);
                    h0 = __hmax2(h0, __hmul2(h0, C001));
                    h1 = __hmax2(h1, __hmul2(h1, C001));
                    A[nt / 2][(nt % 2) * 2 + 0] = h2u(h0);
                    A[nt / 2][(nt % 2) * 2 + 1] = h2u(h1);
                }
            }

            // ---- head: 32 -> 1 via mma (bias in D init, col 0) ----
            uint32_t Dh[2];
            Dh[0] = packh2(s_b3[p], 0.f);
            Dh[1] = Dh[0];
            {
                uint2 b0 = s_bf[(p * TILES_PER_PRED + 24) * 32 + lane];
                uint2 b1 = s_bf[(p * TILES_PER_PRED + 25) * 32 + lane];
                uint32_t br0[2] = {b0.x, b0.y};
                uint32_t br1[2] = {b1.x, b1.y};
                mma16816h(Dh, A[0], br0);
                mma16816h(Dh, A[1], br1);
            }
            if (tig == 0) {
                ph[p][m][0] = fminf(fmaxf(__low2float(u2h(Dh[0])), -1.f), 1.f);   // row g
                ph[p][m][1] = fminf(fmaxf(__low2float(u2h(Dh[1])), -1.f), 1.f);   // row g+8
            }
        }
    }

    // ---- stats: tig==0 lanes own 4 pixels each ----
    if (tig == 0) {
#pragma unroll
        for (int m = 0; m < 2; ++m) {
#pragma unroll
            for (int hh = 0; hh < 2; ++hh) {
                int px = m * 16 + g + hh * 8;
                float x0 = s_tile[wr + 3][px + 3];
                float pa = ph[0][m][hh], pb = ph[1][m][hh], pc = ph[2][m][hh];
                float med = fmaxf(fminf(pa, fmaxf(pb, pc)), fminf(pb, pc));
                float delta = fmodf(x0 - med + 1.0f, 2.0f) - 1.0f;

                if (x0 >= -1.f && x0 <= 1.f) {
                    int idx = (int)floorf((x0 + 1.f) * 128.f);
                    idx = min(max(idx, 0), NBINS - 1);
                    atomicAdd(&s_hist[0][idx], 1u);
                }
                if (delta >= -1.f && delta <= 1.f) {
                    int idx = (int)floorf((delta + 1.f) * 128.f);
                    idx = min(max(idx, 0), NBINS - 1);
                    atomicAdd(&s_hist[1][idx], 1u);
                }
                acc_x += (double)x0 * (double)x0;
                acc_d += (double)delta * (double)delta;
            }
        }
    }

    // ---- reductions ----
#pragma unroll
    for (int o = 16; o > 0; o >>= 1) {
        acc_x += __shfl_down_sync(0xffffffffu, acc_x, o);
        acc_d += __shfl_down_sync(0xffffffffu, acc_d, o);
    }
    if (lane == 0) { s_red[0][wr] = acc_x; s_red[1][wr] = acc_d; }
    __syncthreads();
    if (tid == 0) {
        double sx = 0.0, sd = 0.0;
#pragma unroll
        for (int i = 0; i < NT / 32; ++i) { sx += s_red[0][i]; sd += s_red[1][i]; }
        atomicAdd(&g_sumsq[0], sx);
        atomicAdd(&g_sumsq[1], sd);
    }
    if (tid < NBINS) {
        unsigned c0 = s_hist[0][tid], c1 = s_hist[1][tid];
        if (c0) atomicAdd(&g_hist[0][ch][tid], c0);
        if (c1) atomicAdd(&g_hist[1][ch][tid], c1);
    }
}

__global__ void finalize_kernel(float* out) {
    __shared__ double s_ent[2][8];
    const int tid = threadIdx.x;
    double e0 = 0.0, e1 = 0.0;
    const double res = (double)(IMH * IMW);
    for (int i = tid; i < NCH * NBINS; i += 256) {
        unsigned c0 = ((const unsigned*)g_hist[0])[i];
        unsigned c1 = ((const unsigned*)g_hist[1])[i];
        if (c0) { double pp = (double)c0 / res; e0 -= pp * log2(pp); }
        if (c1) { double pp = (double)c1 / res; e1 -= pp * log2(pp); }
    }
#pragma unroll
    for (int o = 16; o > 0; o >>= 1) {
        e0 += __shfl_down_sync(0xffffffffu, e0, o);
        e1 += __shfl_down_sync(0xffffffffu, e1, o);
    }
    if ((tid & 31) == 0) { s_ent[0][tid >> 5] = e0; s_ent[1][tid >> 5] = e1; }
    __syncthreads();
    if (tid == 0) {
        double E0 = 0.0, E1 = 0.0;
#pragma unroll
        for (int i = 0; i < 8; ++i) { E0 += s_ent[0][i]; E1 += s_ent[1][i]; }
        const double N = (double)NCH * IMH * IMW;
        out[0] = (float)(255.0 * sqrt(g_sumsq[1] / N));   // loss1
        out[1] = (float)(255.0 * sqrt(g_sumsq[0] / N));   // loss0
        out[2] = (float)(E0 / (8.0 * NCH));               // invCR0
        out[3] = (float)(E1 / (8.0 * NCH));               // invCR1
    }
}

extern "C" void kernel_launch(void* const* d_in, const int* in_sizes, int n_in,
                              void* d_out, int out_size) {
    const float* x = (const float*)d_in[0];
    Params prm;
    for (int i = 0; i < 27; ++i) prm.p[i] = (const float*)d_in[1 + i];

    // launch order keeps predict_kernel at index 5 for ncu -s 5 -c 1
    pack_weights_kernel<<<4, 256>>>(prm);                 // 0
    const int per = (ZTOTAL + 3) / 4;
    for (int s = 0; s < 4; ++s)
        zero_slice_kernel<<<(per + 255) / 256, 256>>>(s); // 1-4

    dim3 grid(IMW / 32, IMH / 8, NCH);
    dim3 block(32, 8);
    predict_kernel<<<grid, block>>>(x);                   // 5
    finalize_kernel<<<1, 256>>>((float*)d_out);
}